// round 3
// baseline (speedup 1.0000x reference)
#include <cuda_runtime.h>

#define DIM 64
#define MAXN 100000
#define MAXE 1200000

#define SCAN_TPB 256
#define SCAN_ITEMS 16
#define SCAN_TILE (SCAN_TPB * SCAN_ITEMS)   // 4096

// ---------------------------------------------------------------------------
// Scratch (static device globals; no allocation).
// ---------------------------------------------------------------------------
__device__ int g_deg[MAXN];
__device__ int g_off[MAXN + 1];
__device__ int g_cur[MAXN];
__device__ int g_ssrc[MAXE];
__device__ volatile unsigned long long g_tile[64];  // lookback status: flag<<32 | value

// ---------------------------------------------------------------------------
// K0: zero degree counters + lookback status; set offset sentinel.
// ---------------------------------------------------------------------------
__global__ void k_zero(int n, int nE) {
    int i = blockIdx.x * blockDim.x + threadIdx.x;
    int stride = gridDim.x * blockDim.x;
    for (int j = i; j < n; j += stride) g_deg[j] = 0;
    if (blockIdx.x == 0 && threadIdx.x < 64)
        g_tile[threadIdx.x] = 0ULL;
    if (i == 0) g_off[n] = nE;
}

// ---------------------------------------------------------------------------
// K1: destination-degree histogram (int RED, spread addresses).
// ---------------------------------------------------------------------------
__global__ void k_hist(const int* __restrict__ dst, int nE) {
    int i = blockIdx.x * blockDim.x + threadIdx.x;
    if (i < nE) atomicAdd(&g_deg[dst[i]], 1);
}

// ---------------------------------------------------------------------------
// K2: single-pass exclusive scan of g_deg -> g_off & g_cur.
// Decoupled lookback; tile status packed flag|value in one 64-bit word
// (1 = aggregate ready, 2 = inclusive prefix ready), so no fences needed.
// ---------------------------------------------------------------------------
__global__ __launch_bounds__(SCAN_TPB) void k_scan(int n) {
    __shared__ unsigned s_wsum[8];
    __shared__ unsigned s_prefix;

    int tid = threadIdx.x;
    int lane = tid & 31;
    int wid = tid >> 5;
    int bid = blockIdx.x;
    int base = bid * SCAN_TILE + tid * SCAN_ITEMS;

    // Load 16 items per thread (blocked).
    int items[SCAN_ITEMS];
    bool full = (bid * SCAN_TILE + SCAN_TILE) <= n;
    if (full) {
        const int4* p = reinterpret_cast<const int4*>(g_deg + base);
        #pragma unroll
        for (int q = 0; q < SCAN_ITEMS / 4; ++q) {
            int4 v = p[q];
            items[q * 4 + 0] = v.x; items[q * 4 + 1] = v.y;
            items[q * 4 + 2] = v.z; items[q * 4 + 3] = v.w;
        }
    } else {
        #pragma unroll
        for (int q = 0; q < SCAN_ITEMS; ++q)
            items[q] = (base + q < n) ? g_deg[base + q] : 0;
    }

    unsigned tsum = 0;
    #pragma unroll
    for (int q = 0; q < SCAN_ITEMS; ++q) tsum += (unsigned)items[q];

    // Warp inclusive scan of per-thread sums.
    unsigned inc = tsum;
    #pragma unroll
    for (int d = 1; d < 32; d <<= 1) {
        unsigned u = __shfl_up_sync(0xFFFFFFFFu, inc, d);
        if (lane >= d) inc += u;
    }
    if (lane == 31) s_wsum[wid] = inc;
    __syncthreads();
    if (wid == 0 && lane < 8) {
        unsigned w = s_wsum[lane];
        #pragma unroll
        for (int d = 1; d < 8; d <<= 1) {
            unsigned u = __shfl_up_sync(0xFFu, w, d);
            if (lane >= d) w += u;
        }
        s_wsum[lane] = w;
    }
    __syncthreads();

    unsigned warp_excl = (wid > 0) ? s_wsum[wid - 1] : 0u;
    unsigned block_total = s_wsum[7];
    unsigned thread_excl = warp_excl + (inc - tsum);

    // Lookback (thread 0).
    if (tid == 0) {
        if (bid == 0) {
            g_tile[0] = (2ULL << 32) | (unsigned long long)block_total;
            s_prefix = 0u;
        } else {
            g_tile[bid] = (1ULL << 32) | (unsigned long long)block_total;
            unsigned long long run = 0;
            int t = bid - 1;
            while (true) {
                unsigned long long v;
                do { v = g_tile[t]; } while ((v >> 32) == 0ULL);
                run += (v & 0xFFFFFFFFULL);
                if ((v >> 32) == 2ULL) break;
                --t;
            }
            s_prefix = (unsigned)run;
            g_tile[bid] = (2ULL << 32) | (run + block_total);
        }
    }
    __syncthreads();

    unsigned running = s_prefix + thread_excl;
    if (full) {
        int4* po = reinterpret_cast<int4*>(g_off + base);
        int4* pc = reinterpret_cast<int4*>(g_cur + base);
        #pragma unroll
        for (int q = 0; q < SCAN_ITEMS / 4; ++q) {
            int4 o;
            o.x = (int)running; running += (unsigned)items[q * 4 + 0];
            o.y = (int)running; running += (unsigned)items[q * 4 + 1];
            o.z = (int)running; running += (unsigned)items[q * 4 + 2];
            o.w = (int)running; running += (unsigned)items[q * 4 + 3];
            po[q] = o; pc[q] = o;
        }
    } else {
        #pragma unroll
        for (int q = 0; q < SCAN_ITEMS; ++q) {
            if (base + q < n) {
                g_off[base + q] = (int)running;
                g_cur[base + q] = (int)running;
            }
            running += (unsigned)items[q];
        }
    }
}

// ---------------------------------------------------------------------------
// K3: bucket-fill sorted source indices by destination.
// ---------------------------------------------------------------------------
__global__ void k_fill(const int* __restrict__ src,
                       const int* __restrict__ dst, int nE) {
    int i = blockIdx.x * blockDim.x + threadIdx.x;
    if (i < nE) {
        int d = dst[i];
        int pos = atomicAdd(&g_cur[d], 1);
        g_ssrc[pos] = src[i];
    }
}

// ---------------------------------------------------------------------------
// K4: fused mean-aggregation + linear. 256 threads = 16 node-groups of 16
// lanes. Phase 1: each group gathers & means its node's 64-dim feature into
// smem (transposed). Phase 2: 16x64 @ 64x64 tile GEMM, 4 outputs/thread.
// W staged transposed in smem (L1-resident across blocks on an SM).
// ---------------------------------------------------------------------------
__global__ __launch_bounds__(256) void k_agg_gemm(
    const float* __restrict__ x, const float* __restrict__ W,
    const float* __restrict__ b, float* __restrict__ out, int n) {
    __shared__ float sh[DIM][17];   // [k][local node], pad 17
    __shared__ float sW[DIM][68];   // [k][out col], pad 68

    int tid = threadIdx.x;

    // Stage W transposed: sW[k][j] = W[j*64+k].
    #pragma unroll
    for (int r = 0; r < 16; ++r) {
        int i = r * 256 + tid;
        int j = i >> 6;
        int k = i & 63;
        sW[k][j] = W[i];
    }

    // ---------------- Phase 1: aggregate 16 nodes ----------------
    int node0 = blockIdx.x * 16;
    int g = tid >> 4;          // local node 0..15
    int l = tid & 15;          // lane within group (owns 4 feature floats)
    unsigned mask = 0xFFFFu << (tid & 16);
    int node = node0 + g;

    float4 acc = make_float4(0.f, 0.f, 0.f, 0.f);
    if (node < n) {
        int begin = g_off[node];
        int end = g_off[node + 1];
        for (int base = begin; base < end; base += 16) {
            int m = min(16, end - base);
            int s = (l < m) ? g_ssrc[base + l] : 0;
            int k = 0;
            for (; k + 4 <= m; k += 4) {
                int s0 = __shfl_sync(mask, s, k + 0, 16);
                int s1 = __shfl_sync(mask, s, k + 1, 16);
                int s2 = __shfl_sync(mask, s, k + 2, 16);
                int s3 = __shfl_sync(mask, s, k + 3, 16);
                float4 v0 = *reinterpret_cast<const float4*>(x + (size_t)s0 * DIM + l * 4);
                float4 v1 = *reinterpret_cast<const float4*>(x + (size_t)s1 * DIM + l * 4);
                float4 v2 = *reinterpret_cast<const float4*>(x + (size_t)s2 * DIM + l * 4);
                float4 v3 = *reinterpret_cast<const float4*>(x + (size_t)s3 * DIM + l * 4);
                acc.x += (v0.x + v1.x) + (v2.x + v3.x);
                acc.y += (v0.y + v1.y) + (v2.y + v3.y);
                acc.z += (v0.z + v1.z) + (v2.z + v3.z);
                acc.w += (v0.w + v1.w) + (v2.w + v3.w);
            }
            for (; k < m; ++k) {
                int s0 = __shfl_sync(mask, s, k, 16);
                float4 v0 = *reinterpret_cast<const float4*>(x + (size_t)s0 * DIM + l * 4);
                acc.x += v0.x; acc.y += v0.y; acc.z += v0.z; acc.w += v0.w;
            }
        }
        float invd = 1.0f / fmaxf((float)(end - begin), 1.0f);
        acc.x *= invd; acc.y *= invd; acc.z *= invd; acc.w *= invd;
    }
    sh[l * 4 + 0][g] = acc.x;
    sh[l * 4 + 1][g] = acc.y;
    sh[l * 4 + 2][g] = acc.z;
    sh[l * 4 + 3][g] = acc.w;
    __syncthreads();

    // ---------------- Phase 2: tile GEMM ----------------
    int nl = tid & 15;         // local node
    int jc = (tid >> 4) * 4;   // output col group

    float4 accum = *reinterpret_cast<const float4*>(b + jc);
    #pragma unroll
    for (int k = 0; k < DIM; ++k) {
        float hv = sh[k][nl];
        float4 wv = *reinterpret_cast<const float4*>(&sW[k][jc]);
        accum.x += hv * wv.x;
        accum.y += hv * wv.y;
        accum.z += hv * wv.z;
        accum.w += hv * wv.w;
    }

    int onode = node0 + nl;
    if (onode < n)
        *reinterpret_cast<float4*>(out + (size_t)onode * DIM + jc) = accum;
}

// ---------------------------------------------------------------------------
// Launch. Inputs: x [N*64 f32], src [E i32], dst [E i32], W [64*64 f32],
// b [64 f32]. Output: [N*64 f32].
// ---------------------------------------------------------------------------
extern "C" void kernel_launch(void* const* d_in, const int* in_sizes, int n_in,
                              void* d_out, int out_size) {
    const float* x   = (const float*)d_in[0];
    const int*   src = (const int*)d_in[1];
    const int*   dst = (const int*)d_in[2];
    const float* W   = (const float*)d_in[3];
    const float* b   = (const float*)d_in[4];
    float* out = (float*)d_out;

    int nNodes = in_sizes[0] / DIM;
    int nEdges = in_sizes[1];

    int eBlocks = (nEdges + 255) / 256;
    int scanTiles = (nNodes + SCAN_TILE - 1) / SCAN_TILE;

    k_zero<<<148, 256>>>(nNodes, nEdges);
    k_hist<<<eBlocks, 256>>>(dst, nEdges);
    k_scan<<<scanTiles, SCAN_TPB>>>(nNodes);
    k_fill<<<eBlocks, 256>>>(src, dst, nEdges);
    k_agg_gemm<<<(nNodes + 15) / 16, 256>>>(x, W, b, out, nNodes);
}

// round 4
// speedup vs baseline: 1.1029x; 1.1029x over previous
#include <cuda_runtime.h>

#define DIM 64
#define MAXN 100000
#define MAXE 1200000

#define SCAN_TPB 256
#define SCAN_ITEMS 16
#define SCAN_TILE (SCAN_TPB * SCAN_ITEMS)   // 4096

// ---------------------------------------------------------------------------
// Scratch (static device globals; zero-initialized at module load).
// Invariant maintained across launches: g_deg == 0 at kernel_launch entry
// (k_scan re-zeros it after reading); g_tile is zeroed by k_hist each launch.
// ---------------------------------------------------------------------------
__device__ int g_deg[MAXN];
__device__ int g_off[MAXN + 1];
__device__ int g_cur[MAXN];
__device__ int g_ssrc[MAXE];
__device__ float g_h[(size_t)MAXN * DIM];
__device__ volatile unsigned long long g_tile[64];  // flag<<32 | value

// ---------------------------------------------------------------------------
// K1: destination-degree histogram. 4 edges/thread via int4 loads.
// Block 0 also zeros the scan lookback statuses and sets the CSR sentinel
// (ordering vs k_scan guaranteed by the kernel boundary).
// ---------------------------------------------------------------------------
__global__ void k_hist(const int* __restrict__ dst, int nE, int n) {
    int t = blockIdx.x * blockDim.x + threadIdx.x;
    if (blockIdx.x == 0) {
        if (threadIdx.x < 64) g_tile[threadIdx.x] = 0ULL;
        if (threadIdx.x == 64) g_off[n] = nE;
    }
    int i4 = t * 4;
    if (i4 + 4 <= nE) {
        int4 d = *reinterpret_cast<const int4*>(dst + i4);
        atomicAdd(&g_deg[d.x], 1);
        atomicAdd(&g_deg[d.y], 1);
        atomicAdd(&g_deg[d.z], 1);
        atomicAdd(&g_deg[d.w], 1);
    } else {
        for (int i = i4; i < nE; ++i) atomicAdd(&g_deg[dst[i]], 1);
    }
}

// ---------------------------------------------------------------------------
// K2: single-pass exclusive scan g_deg -> g_off & g_cur (decoupled lookback,
// packed 64-bit flag|value statuses). Re-zeros g_deg for the next launch.
// ---------------------------------------------------------------------------
__global__ __launch_bounds__(SCAN_TPB) void k_scan(int n) {
    __shared__ unsigned s_wsum[8];
    __shared__ unsigned s_prefix;

    int tid = threadIdx.x;
    int lane = tid & 31;
    int wid = tid >> 5;
    int bid = blockIdx.x;
    int base = bid * SCAN_TILE + tid * SCAN_ITEMS;

    int items[SCAN_ITEMS];
    bool full = (bid * SCAN_TILE + SCAN_TILE) <= n;
    if (full) {
        const int4* p = reinterpret_cast<const int4*>(g_deg + base);
        #pragma unroll
        for (int q = 0; q < SCAN_ITEMS / 4; ++q) {
            int4 v = p[q];
            items[q * 4 + 0] = v.x; items[q * 4 + 1] = v.y;
            items[q * 4 + 2] = v.z; items[q * 4 + 3] = v.w;
        }
        // restore the zero invariant for the next launch
        int4 z = make_int4(0, 0, 0, 0);
        int4* pz = reinterpret_cast<int4*>(g_deg + base);
        #pragma unroll
        for (int q = 0; q < SCAN_ITEMS / 4; ++q) pz[q] = z;
    } else {
        #pragma unroll
        for (int q = 0; q < SCAN_ITEMS; ++q) {
            items[q] = (base + q < n) ? g_deg[base + q] : 0;
            if (base + q < n) g_deg[base + q] = 0;
        }
    }

    unsigned tsum = 0;
    #pragma unroll
    for (int q = 0; q < SCAN_ITEMS; ++q) tsum += (unsigned)items[q];

    unsigned inc = tsum;
    #pragma unroll
    for (int d = 1; d < 32; d <<= 1) {
        unsigned u = __shfl_up_sync(0xFFFFFFFFu, inc, d);
        if (lane >= d) inc += u;
    }
    if (lane == 31) s_wsum[wid] = inc;
    __syncthreads();
    if (wid == 0 && lane < 8) {
        unsigned w = s_wsum[lane];
        #pragma unroll
        for (int d = 1; d < 8; d <<= 1) {
            unsigned u = __shfl_up_sync(0xFFu, w, d);
            if (lane >= d) w += u;
        }
        s_wsum[lane] = w;
    }
    __syncthreads();

    unsigned warp_excl = (wid > 0) ? s_wsum[wid - 1] : 0u;
    unsigned block_total = s_wsum[7];
    unsigned thread_excl = warp_excl + (inc - tsum);

    if (tid == 0) {
        if (bid == 0) {
            g_tile[0] = (2ULL << 32) | (unsigned long long)block_total;
            s_prefix = 0u;
        } else {
            g_tile[bid] = (1ULL << 32) | (unsigned long long)block_total;
            unsigned long long run = 0;
            int t = bid - 1;
            while (true) {
                unsigned long long v;
                do { v = g_tile[t]; } while ((v >> 32) == 0ULL);
                run += (v & 0xFFFFFFFFULL);
                if ((v >> 32) == 2ULL) break;
                --t;
            }
            s_prefix = (unsigned)run;
            g_tile[bid] = (2ULL << 32) | (run + block_total);
        }
    }
    __syncthreads();

    unsigned running = s_prefix + thread_excl;
    if (full) {
        int4* po = reinterpret_cast<int4*>(g_off + base);
        int4* pc = reinterpret_cast<int4*>(g_cur + base);
        #pragma unroll
        for (int q = 0; q < SCAN_ITEMS / 4; ++q) {
            int4 o;
            o.x = (int)running; running += (unsigned)items[q * 4 + 0];
            o.y = (int)running; running += (unsigned)items[q * 4 + 1];
            o.z = (int)running; running += (unsigned)items[q * 4 + 2];
            o.w = (int)running; running += (unsigned)items[q * 4 + 3];
            po[q] = o; pc[q] = o;
        }
    } else {
        #pragma unroll
        for (int q = 0; q < SCAN_ITEMS; ++q) {
            if (base + q < n) {
                g_off[base + q] = (int)running;
                g_cur[base + q] = (int)running;
            }
            running += (unsigned)items[q];
        }
    }
}

// ---------------------------------------------------------------------------
// K3: bucket-fill sorted sources. 4 edges/thread via int4 loads.
// ---------------------------------------------------------------------------
__global__ void k_fill(const int* __restrict__ src,
                       const int* __restrict__ dst, int nE) {
    int t = blockIdx.x * blockDim.x + threadIdx.x;
    int i4 = t * 4;
    if (i4 + 4 <= nE) {
        int4 d = *reinterpret_cast<const int4*>(dst + i4);
        int4 s = *reinterpret_cast<const int4*>(src + i4);
        int p0 = atomicAdd(&g_cur[d.x], 1);
        int p1 = atomicAdd(&g_cur[d.y], 1);
        int p2 = atomicAdd(&g_cur[d.z], 1);
        int p3 = atomicAdd(&g_cur[d.w], 1);
        g_ssrc[p0] = s.x;
        g_ssrc[p1] = s.y;
        g_ssrc[p2] = s.z;
        g_ssrc[p3] = s.w;
    } else {
        for (int i = i4; i < nE; ++i) {
            int pos = atomicAdd(&g_cur[dst[i]], 1);
            g_ssrc[pos] = src[i];
        }
    }
}

// ---------------------------------------------------------------------------
// K4: atomic-free aggregation. One 16-lane group per node; each lane owns a
// float4 of the row. Coalesced 256B row gathers, register accumulation.
// ---------------------------------------------------------------------------
__global__ __launch_bounds__(256) void k_agg(const float* __restrict__ x, int n) {
    int node = (blockIdx.x * blockDim.x + threadIdx.x) >> 4;
    int l = threadIdx.x & 15;
    unsigned mask = 0xFFFFu << (threadIdx.x & 16);
    if (node >= n) return;

    int begin = g_off[node];
    int end   = g_off[node + 1];
    float4 acc = make_float4(0.f, 0.f, 0.f, 0.f);

    for (int base = begin; base < end; base += 16) {
        int m = min(16, end - base);
        int s = (l < m) ? g_ssrc[base + l] : 0;
        int k = 0;
        for (; k + 4 <= m; k += 4) {
            int s0 = __shfl_sync(mask, s, k + 0, 16);
            int s1 = __shfl_sync(mask, s, k + 1, 16);
            int s2 = __shfl_sync(mask, s, k + 2, 16);
            int s3 = __shfl_sync(mask, s, k + 3, 16);
            float4 v0 = *reinterpret_cast<const float4*>(x + (size_t)s0 * DIM + l * 4);
            float4 v1 = *reinterpret_cast<const float4*>(x + (size_t)s1 * DIM + l * 4);
            float4 v2 = *reinterpret_cast<const float4*>(x + (size_t)s2 * DIM + l * 4);
            float4 v3 = *reinterpret_cast<const float4*>(x + (size_t)s3 * DIM + l * 4);
            acc.x += (v0.x + v1.x) + (v2.x + v3.x);
            acc.y += (v0.y + v1.y) + (v2.y + v3.y);
            acc.z += (v0.z + v1.z) + (v2.z + v3.z);
            acc.w += (v0.w + v1.w) + (v2.w + v3.w);
        }
        for (; k < m; ++k) {
            int s0 = __shfl_sync(mask, s, k, 16);
            float4 v0 = *reinterpret_cast<const float4*>(x + (size_t)s0 * DIM + l * 4);
            acc.x += v0.x; acc.y += v0.y; acc.z += v0.z; acc.w += v0.w;
        }
    }

    float invd = 1.0f / fmaxf((float)(end - begin), 1.0f);
    acc.x *= invd; acc.y *= invd; acc.z *= invd; acc.w *= invd;
    *reinterpret_cast<float4*>(g_h + (size_t)node * DIM + l * 4) = acc;
}

// ---------------------------------------------------------------------------
// K5: linear out = h @ W^T + b. 64-node x 64-col tile per 256-thread block,
// 4x4 register tiles, float4 smem loads.
// ---------------------------------------------------------------------------
__global__ __launch_bounds__(256) void k_gemm(
    const float* __restrict__ W, const float* __restrict__ b,
    float* __restrict__ out, int nNodes) {
    __shared__ float sW[DIM][68];
    __shared__ float sh[DIM][68];
    int tid = threadIdx.x;

    for (int i = tid; i < DIM * DIM; i += 256) {
        int j = i >> 6;
        int k = i & 63;
        sW[k][j] = W[i];
    }

    int n0 = blockIdx.x * 64;
    #pragma unroll
    for (int r = 0; r < 16; ++r) {
        int flat = r * 256 + tid;
        int nl = flat >> 6;
        int k  = flat & 63;
        int n = n0 + nl;
        float v = 0.f;
        if (n < nNodes) v = g_h[(size_t)n * DIM + k];
        sh[k][nl] = v;
    }
    __syncthreads();

    int tx = tid & 15;
    int ty = tid >> 4;
    int jc  = tx * 4;
    int nl0 = ty * 4;

    float accum[4][4];
    float4 bb = *reinterpret_cast<const float4*>(b + jc);
    #pragma unroll
    for (int a = 0; a < 4; ++a) {
        accum[a][0] = bb.x; accum[a][1] = bb.y;
        accum[a][2] = bb.z; accum[a][3] = bb.w;
    }

    #pragma unroll
    for (int k = 0; k < DIM; ++k) {
        float4 hv = *reinterpret_cast<const float4*>(&sh[k][nl0]);
        float4 wv = *reinterpret_cast<const float4*>(&sW[k][jc]);
        float ha[4] = {hv.x, hv.y, hv.z, hv.w};
        float wa[4] = {wv.x, wv.y, wv.z, wv.w};
        #pragma unroll
        for (int a = 0; a < 4; ++a)
            #pragma unroll
            for (int c2 = 0; c2 < 4; ++c2)
                accum[a][c2] += ha[a] * wa[c2];
    }

    #pragma unroll
    for (int a = 0; a < 4; ++a) {
        int n = n0 + nl0 + a;
        if (n < nNodes) {
            float4 o = make_float4(accum[a][0], accum[a][1],
                                   accum[a][2], accum[a][3]);
            *reinterpret_cast<float4*>(out + (size_t)n * DIM + jc) = o;
        }
    }
}

// ---------------------------------------------------------------------------
// Launch. Inputs: x [N*64 f32], src [E i32], dst [E i32], W [64*64 f32],
// b [64 f32]. Output: [N*64 f32].
// ---------------------------------------------------------------------------
extern "C" void kernel_launch(void* const* d_in, const int* in_sizes, int n_in,
                              void* d_out, int out_size) {
    const float* x   = (const float*)d_in[0];
    const int*   src = (const int*)d_in[1];
    const int*   dst = (const int*)d_in[2];
    const float* W   = (const float*)d_in[3];
    const float* b   = (const float*)d_in[4];
    float* out = (float*)d_out;

    int nNodes = in_sizes[0] / DIM;
    int nEdges = in_sizes[1];

    int e4Blocks = ((nEdges + 3) / 4 + 255) / 256;
    int scanTiles = (nNodes + SCAN_TILE - 1) / SCAN_TILE;

    k_hist<<<e4Blocks, 256>>>(dst, nEdges, nNodes);
    k_scan<<<scanTiles, SCAN_TPB>>>(nNodes);
    k_fill<<<e4Blocks, 256>>>(src, dst, nEdges);
    k_agg<<<(nNodes * 16 + 255) / 256, 256>>>(x, nNodes);
    k_gemm<<<(nNodes + 63) / 64, 256>>>(W, b, out, nNodes);
}

// round 5
// speedup vs baseline: 1.1547x; 1.0470x over previous
#include <cuda_runtime.h>

#define DIM 64
#define MAXN 100000
#define MAXE 1200000

#define SCAN_TPB 256
#define SCAN_ITEMS 16
#define SCAN_TILE (SCAN_TPB * SCAN_ITEMS)   // 4096

// ---------------------------------------------------------------------------
// Scratch (static device globals; zero-initialized at module load).
// Invariant: g_deg == 0 at kernel_launch entry (k_scan re-zeros after use).
// ---------------------------------------------------------------------------
__device__ int g_deg[MAXN];
__device__ int g_off[MAXN + 1];
__device__ int g_cur[MAXN];
__device__ int g_ssrc[MAXE];
__device__ float g_h[(size_t)MAXN * DIM];
__device__ int g_bsum[64];

// ---------------------------------------------------------------------------
// K1: destination-degree histogram, 4 edges/thread (int4). Block 0 sets the
// CSR sentinel (visible to later kernels via the launch boundary).
// ---------------------------------------------------------------------------
__global__ void k_hist(const int* __restrict__ dst, int nE, int n) {
    int t = blockIdx.x * blockDim.x + threadIdx.x;
    if (t == 0) g_off[n] = nE;
    int i4 = t * 4;
    if (i4 + 4 <= nE) {
        int4 d = *reinterpret_cast<const int4*>(dst + i4);
        atomicAdd(&g_deg[d.x], 1);
        atomicAdd(&g_deg[d.y], 1);
        atomicAdd(&g_deg[d.z], 1);
        atomicAdd(&g_deg[d.w], 1);
    } else {
        for (int i = i4; i < nE; ++i) atomicAdd(&g_deg[dst[i]], 1);
    }
}

// ---------------------------------------------------------------------------
// K2a: per-tile reduction of g_deg -> g_bsum[tile]. No cross-block deps.
// ---------------------------------------------------------------------------
__global__ __launch_bounds__(SCAN_TPB) void k_reduce(int n) {
    int base = blockIdx.x * SCAN_TILE + threadIdx.x * SCAN_ITEMS;
    unsigned s = 0;
    if (base + SCAN_ITEMS <= n) {
        const int4* p = reinterpret_cast<const int4*>(g_deg + base);
        #pragma unroll
        for (int q = 0; q < SCAN_ITEMS / 4; ++q) {
            int4 v = p[q];
            s += (unsigned)(v.x + v.y) + (unsigned)(v.z + v.w);
        }
    } else {
        for (int q = 0; q < SCAN_ITEMS; ++q)
            if (base + q < n) s += (unsigned)g_deg[base + q];
    }
    #pragma unroll
    for (int d = 16; d; d >>= 1) s += __shfl_down_sync(0xFFFFFFFFu, s, d);
    __shared__ unsigned ws[8];
    if ((threadIdx.x & 31) == 0) ws[threadIdx.x >> 5] = s;
    __syncthreads();
    if (threadIdx.x < 8) {
        unsigned v = ws[threadIdx.x];
        #pragma unroll
        for (int d = 4; d; d >>= 1) v += __shfl_down_sync(0xFFu, v, d);
        if (threadIdx.x == 0) g_bsum[blockIdx.x] = (int)v;
    }
}

// ---------------------------------------------------------------------------
// K2b: per-tile scan with base = sum of preceding tile sums (<=64 values,
// one warp-reduce; no polling, no serialization). Writes g_off & g_cur,
// re-zeros g_deg for the next launch.
// ---------------------------------------------------------------------------
__global__ __launch_bounds__(SCAN_TPB) void k_scan(int n) {
    __shared__ unsigned s_wsum[8];
    __shared__ unsigned s_base;

    int tid = threadIdx.x;
    int lane = tid & 31;
    int wid = tid >> 5;
    int bid = blockIdx.x;
    int base = bid * SCAN_TILE + tid * SCAN_ITEMS;

    if (wid == 0) {
        unsigned v = 0;
        if (lane < bid) v = (unsigned)g_bsum[lane];
        if (lane + 32 < bid) v += (unsigned)g_bsum[lane + 32];
        #pragma unroll
        for (int d = 16; d; d >>= 1) v += __shfl_down_sync(0xFFFFFFFFu, v, d);
        if (lane == 0) s_base = v;
    }

    int items[SCAN_ITEMS];
    bool full = (base + SCAN_ITEMS) <= n;
    if (full) {
        const int4* p = reinterpret_cast<const int4*>(g_deg + base);
        #pragma unroll
        for (int q = 0; q < SCAN_ITEMS / 4; ++q) {
            int4 v = p[q];
            items[q * 4 + 0] = v.x; items[q * 4 + 1] = v.y;
            items[q * 4 + 2] = v.z; items[q * 4 + 3] = v.w;
        }
        int4 z = make_int4(0, 0, 0, 0);
        int4* pz = reinterpret_cast<int4*>(g_deg + base);
        #pragma unroll
        for (int q = 0; q < SCAN_ITEMS / 4; ++q) pz[q] = z;
    } else {
        #pragma unroll
        for (int q = 0; q < SCAN_ITEMS; ++q) {
            items[q] = (base + q < n) ? g_deg[base + q] : 0;
            if (base + q < n) g_deg[base + q] = 0;
        }
    }

    unsigned tsum = 0;
    #pragma unroll
    for (int q = 0; q < SCAN_ITEMS; ++q) tsum += (unsigned)items[q];

    unsigned inc = tsum;
    #pragma unroll
    for (int d = 1; d < 32; d <<= 1) {
        unsigned u = __shfl_up_sync(0xFFFFFFFFu, inc, d);
        if (lane >= d) inc += u;
    }
    if (lane == 31) s_wsum[wid] = inc;
    __syncthreads();
    if (wid == 0 && lane < 8) {
        unsigned w = s_wsum[lane];
        #pragma unroll
        for (int d = 1; d < 8; d <<= 1) {
            unsigned u = __shfl_up_sync(0xFFu, w, d);
            if (lane >= d) w += u;
        }
        s_wsum[lane] = w;
    }
    __syncthreads();

    unsigned warp_excl = (wid > 0) ? s_wsum[wid - 1] : 0u;
    unsigned running = s_base + warp_excl + (inc - tsum);

    if (full) {
        int4* po = reinterpret_cast<int4*>(g_off + base);
        int4* pc = reinterpret_cast<int4*>(g_cur + base);
        #pragma unroll
        for (int q = 0; q < SCAN_ITEMS / 4; ++q) {
            int4 o;
            o.x = (int)running; running += (unsigned)items[q * 4 + 0];
            o.y = (int)running; running += (unsigned)items[q * 4 + 1];
            o.z = (int)running; running += (unsigned)items[q * 4 + 2];
            o.w = (int)running; running += (unsigned)items[q * 4 + 3];
            po[q] = o; pc[q] = o;
        }
    } else {
        #pragma unroll
        for (int q = 0; q < SCAN_ITEMS; ++q) {
            if (base + q < n) {
                g_off[base + q] = (int)running;
                g_cur[base + q] = (int)running;
            }
            running += (unsigned)items[q];
        }
    }
}

// ---------------------------------------------------------------------------
// K3: bucket-fill sorted sources, 4 edges/thread (int4).
// ---------------------------------------------------------------------------
__global__ void k_fill(const int* __restrict__ src,
                       const int* __restrict__ dst, int nE) {
    int t = blockIdx.x * blockDim.x + threadIdx.x;
    int i4 = t * 4;
    if (i4 + 4 <= nE) {
        int4 d = *reinterpret_cast<const int4*>(dst + i4);
        int4 s = *reinterpret_cast<const int4*>(src + i4);
        int p0 = atomicAdd(&g_cur[d.x], 1);
        int p1 = atomicAdd(&g_cur[d.y], 1);
        int p2 = atomicAdd(&g_cur[d.z], 1);
        int p3 = atomicAdd(&g_cur[d.w], 1);
        g_ssrc[p0] = s.x;
        g_ssrc[p1] = s.y;
        g_ssrc[p2] = s.z;
        g_ssrc[p3] = s.w;
    } else {
        for (int i = i4; i < nE; ++i) {
            int pos = atomicAdd(&g_cur[dst[i]], 1);
            g_ssrc[pos] = src[i];
        }
    }
}

// ---------------------------------------------------------------------------
// K4: aggregation. One 16-lane group per node; each lane owns a float4 of
// the 64-float row. Edge indices loaded directly by all lanes (broadcast,
// L1-resident) — no shuffles — and 8 gathers kept in flight.
// ---------------------------------------------------------------------------
__global__ __launch_bounds__(256) void k_agg(const float* __restrict__ x, int n) {
    int node = (blockIdx.x * blockDim.x + threadIdx.x) >> 4;
    int l = threadIdx.x & 15;
    if (node >= n) return;

    int begin = g_off[node];
    int end   = g_off[node + 1];
    const float4* xv = reinterpret_cast<const float4*>(x);

    float4 acc = make_float4(0.f, 0.f, 0.f, 0.f);
    int i = begin;

    #pragma unroll 1
    for (; i + 8 <= end; i += 8) {
        int e0 = __ldg(&g_ssrc[i + 0]);
        int e1 = __ldg(&g_ssrc[i + 1]);
        int e2 = __ldg(&g_ssrc[i + 2]);
        int e3 = __ldg(&g_ssrc[i + 3]);
        int e4 = __ldg(&g_ssrc[i + 4]);
        int e5 = __ldg(&g_ssrc[i + 5]);
        int e6 = __ldg(&g_ssrc[i + 6]);
        int e7 = __ldg(&g_ssrc[i + 7]);
        float4 v0 = xv[(size_t)e0 * 16 + l];
        float4 v1 = xv[(size_t)e1 * 16 + l];
        float4 v2 = xv[(size_t)e2 * 16 + l];
        float4 v3 = xv[(size_t)e3 * 16 + l];
        float4 v4 = xv[(size_t)e4 * 16 + l];
        float4 v5 = xv[(size_t)e5 * 16 + l];
        float4 v6 = xv[(size_t)e6 * 16 + l];
        float4 v7 = xv[(size_t)e7 * 16 + l];
        acc.x += ((v0.x + v1.x) + (v2.x + v3.x)) + ((v4.x + v5.x) + (v6.x + v7.x));
        acc.y += ((v0.y + v1.y) + (v2.y + v3.y)) + ((v4.y + v5.y) + (v6.y + v7.y));
        acc.z += ((v0.z + v1.z) + (v2.z + v3.z)) + ((v4.z + v5.z) + (v6.z + v7.z));
        acc.w += ((v0.w + v1.w) + (v2.w + v3.w)) + ((v4.w + v5.w) + (v6.w + v7.w));
    }
    if (i + 4 <= end) {
        int e0 = __ldg(&g_ssrc[i + 0]);
        int e1 = __ldg(&g_ssrc[i + 1]);
        int e2 = __ldg(&g_ssrc[i + 2]);
        int e3 = __ldg(&g_ssrc[i + 3]);
        float4 v0 = xv[(size_t)e0 * 16 + l];
        float4 v1 = xv[(size_t)e1 * 16 + l];
        float4 v2 = xv[(size_t)e2 * 16 + l];
        float4 v3 = xv[(size_t)e3 * 16 + l];
        acc.x += (v0.x + v1.x) + (v2.x + v3.x);
        acc.y += (v0.y + v1.y) + (v2.y + v3.y);
        acc.z += (v0.z + v1.z) + (v2.z + v3.z);
        acc.w += (v0.w + v1.w) + (v2.w + v3.w);
        i += 4;
    }
    #pragma unroll 1
    for (; i < end; ++i) {
        int e0 = __ldg(&g_ssrc[i]);
        float4 v0 = xv[(size_t)e0 * 16 + l];
        acc.x += v0.x; acc.y += v0.y; acc.z += v0.z; acc.w += v0.w;
    }

    float invd = 1.0f / fmaxf((float)(end - begin), 1.0f);
    acc.x *= invd; acc.y *= invd; acc.z *= invd; acc.w *= invd;
    *reinterpret_cast<float4*>(g_h + (size_t)node * DIM + l * 4) = acc;
}

// ---------------------------------------------------------------------------
// K5: linear out = h @ W^T + b. 64x64 tile per 256-thread block, 4x4
// register tiles, float4 smem loads.
// ---------------------------------------------------------------------------
__global__ __launch_bounds__(256) void k_gemm(
    const float* __restrict__ W, const float* __restrict__ b,
    float* __restrict__ out, int nNodes) {
    __shared__ float sW[DIM][68];
    __shared__ float sh[DIM][68];
    int tid = threadIdx.x;

    for (int i = tid; i < DIM * DIM; i += 256) {
        int j = i >> 6;
        int k = i & 63;
        sW[k][j] = W[i];
    }

    int n0 = blockIdx.x * 64;
    #pragma unroll
    for (int r = 0; r < 16; ++r) {
        int flat = r * 256 + tid;
        int nl = flat >> 6;
        int k  = flat & 63;
        int n = n0 + nl;
        float v = 0.f;
        if (n < nNodes) v = g_h[(size_t)n * DIM + k];
        sh[k][nl] = v;
    }
    __syncthreads();

    int tx = tid & 15;
    int ty = tid >> 4;
    int jc  = tx * 4;
    int nl0 = ty * 4;

    float accum[4][4];
    float4 bb = *reinterpret_cast<const float4*>(b + jc);
    #pragma unroll
    for (int a = 0; a < 4; ++a) {
        accum[a][0] = bb.x; accum[a][1] = bb.y;
        accum[a][2] = bb.z; accum[a][3] = bb.w;
    }

    #pragma unroll
    for (int k = 0; k < DIM; ++k) {
        float4 hv = *reinterpret_cast<const float4*>(&sh[k][nl0]);
        float4 wv = *reinterpret_cast<const float4*>(&sW[k][jc]);
        float ha[4] = {hv.x, hv.y, hv.z, hv.w};
        float wa[4] = {wv.x, wv.y, wv.z, wv.w};
        #pragma unroll
        for (int a = 0; a < 4; ++a)
            #pragma unroll
            for (int c2 = 0; c2 < 4; ++c2)
                accum[a][c2] += ha[a] * wa[c2];
    }

    #pragma unroll
    for (int a = 0; a < 4; ++a) {
        int n = n0 + nl0 + a;
        if (n < nNodes) {
            float4 o = make_float4(accum[a][0], accum[a][1],
                                   accum[a][2], accum[a][3]);
            *reinterpret_cast<float4*>(out + (size_t)n * DIM + jc) = o;
        }
    }
}

// ---------------------------------------------------------------------------
// Launch. Inputs: x [N*64 f32], src [E i32], dst [E i32], W [64*64 f32],
// b [64 f32]. Output: [N*64 f32].
// ---------------------------------------------------------------------------
extern "C" void kernel_launch(void* const* d_in, const int* in_sizes, int n_in,
                              void* d_out, int out_size) {
    const float* x   = (const float*)d_in[0];
    const int*   src = (const int*)d_in[1];
    const int*   dst = (const int*)d_in[2];
    const float* W   = (const float*)d_in[3];
    const float* b   = (const float*)d_in[4];
    float* out = (float*)d_out;

    int nNodes = in_sizes[0] / DIM;
    int nEdges = in_sizes[1];

    int e4Blocks = ((nEdges + 3) / 4 + 255) / 256;
    int scanTiles = (nNodes + SCAN_TILE - 1) / SCAN_TILE;

    k_hist<<<e4Blocks, 256>>>(dst, nEdges, nNodes);
    k_reduce<<<scanTiles, SCAN_TPB>>>(nNodes);
    k_scan<<<scanTiles, SCAN_TPB>>>(nNodes);
    k_fill<<<e4Blocks, 256>>>(src, dst, nEdges);
    k_agg<<<(nNodes * 16 + 255) / 256, 256>>>(x, nNodes);
    k_gemm<<<(nNodes + 63) / 64, 256>>>(W, b, out, nNodes);
}

// round 6
// speedup vs baseline: 1.1771x; 1.0194x over previous
#include <cuda_runtime.h>

#define DIM 64
#define MAXN 100000
#define MAXE 1200000

#define SCAN_TPB 256
#define SCAN_ITEMS 16
#define SCAN_TILE (SCAN_TPB * SCAN_ITEMS)   // 4096

// ---------------------------------------------------------------------------
// Scratch (static device globals; zero-initialized at module load).
// Invariant: g_deg == 0 at kernel_launch entry (k_scan re-zeros after use).
// ---------------------------------------------------------------------------
__device__ int g_deg[MAXN];
__device__ int g_off[MAXN + 1];
__device__ int g_rank[MAXE];
__device__ int g_ssrc[MAXE];
__device__ float g_h[(size_t)MAXN * DIM];
__device__ int g_bsum[64];

// ---------------------------------------------------------------------------
// K1: destination-degree histogram, 4 edges/thread (int4). The atomic's
// return value IS the edge's rank within its destination bucket — saved to
// g_rank so the fill pass needs no atomics at all.
// ---------------------------------------------------------------------------
__global__ void k_hist(const int* __restrict__ dst, int nE, int n) {
    int t = blockIdx.x * blockDim.x + threadIdx.x;
    if (t == 0) g_off[n] = nE;
    int i4 = t * 4;
    if (i4 + 4 <= nE) {
        int4 d = *reinterpret_cast<const int4*>(dst + i4);
        int4 r;
        r.x = atomicAdd(&g_deg[d.x], 1);
        r.y = atomicAdd(&g_deg[d.y], 1);
        r.z = atomicAdd(&g_deg[d.z], 1);
        r.w = atomicAdd(&g_deg[d.w], 1);
        *reinterpret_cast<int4*>(g_rank + i4) = r;
    } else {
        for (int i = i4; i < nE; ++i)
            g_rank[i] = atomicAdd(&g_deg[dst[i]], 1);
    }
}

// ---------------------------------------------------------------------------
// K2a: per-tile reduction of g_deg -> g_bsum[tile].
// ---------------------------------------------------------------------------
__global__ __launch_bounds__(SCAN_TPB) void k_reduce(int n) {
    int base = blockIdx.x * SCAN_TILE + threadIdx.x * SCAN_ITEMS;
    unsigned s = 0;
    if (base + SCAN_ITEMS <= n) {
        const int4* p = reinterpret_cast<const int4*>(g_deg + base);
        #pragma unroll
        for (int q = 0; q < SCAN_ITEMS / 4; ++q) {
            int4 v = p[q];
            s += (unsigned)(v.x + v.y) + (unsigned)(v.z + v.w);
        }
    } else {
        for (int q = 0; q < SCAN_ITEMS; ++q)
            if (base + q < n) s += (unsigned)g_deg[base + q];
    }
    #pragma unroll
    for (int d = 16; d; d >>= 1) s += __shfl_down_sync(0xFFFFFFFFu, s, d);
    __shared__ unsigned ws[8];
    if ((threadIdx.x & 31) == 0) ws[threadIdx.x >> 5] = s;
    __syncthreads();
    if (threadIdx.x < 8) {
        unsigned v = ws[threadIdx.x];
        #pragma unroll
        for (int d = 4; d; d >>= 1) v += __shfl_down_sync(0xFFu, v, d);
        if (threadIdx.x == 0) g_bsum[blockIdx.x] = (int)v;
    }
}

// ---------------------------------------------------------------------------
// K2b: per-tile scan; base = sum of preceding tile sums (one warp-reduce).
// Writes g_off; re-zeros g_deg for the next launch.
// ---------------------------------------------------------------------------
__global__ __launch_bounds__(SCAN_TPB) void k_scan(int n) {
    __shared__ unsigned s_wsum[8];
    __shared__ unsigned s_base;

    int tid = threadIdx.x;
    int lane = tid & 31;
    int wid = tid >> 5;
    int bid = blockIdx.x;
    int base = bid * SCAN_TILE + tid * SCAN_ITEMS;

    if (wid == 0) {
        unsigned v = 0;
        if (lane < bid) v = (unsigned)g_bsum[lane];
        if (lane + 32 < bid) v += (unsigned)g_bsum[lane + 32];
        #pragma unroll
        for (int d = 16; d; d >>= 1) v += __shfl_down_sync(0xFFFFFFFFu, v, d);
        if (lane == 0) s_base = v;
    }

    int items[SCAN_ITEMS];
    bool full = (base + SCAN_ITEMS) <= n;
    if (full) {
        const int4* p = reinterpret_cast<const int4*>(g_deg + base);
        #pragma unroll
        for (int q = 0; q < SCAN_ITEMS / 4; ++q) {
            int4 v = p[q];
            items[q * 4 + 0] = v.x; items[q * 4 + 1] = v.y;
            items[q * 4 + 2] = v.z; items[q * 4 + 3] = v.w;
        }
        int4 z = make_int4(0, 0, 0, 0);
        int4* pz = reinterpret_cast<int4*>(g_deg + base);
        #pragma unroll
        for (int q = 0; q < SCAN_ITEMS / 4; ++q) pz[q] = z;
    } else {
        #pragma unroll
        for (int q = 0; q < SCAN_ITEMS; ++q) {
            items[q] = (base + q < n) ? g_deg[base + q] : 0;
            if (base + q < n) g_deg[base + q] = 0;
        }
    }

    unsigned tsum = 0;
    #pragma unroll
    for (int q = 0; q < SCAN_ITEMS; ++q) tsum += (unsigned)items[q];

    unsigned inc = tsum;
    #pragma unroll
    for (int d = 1; d < 32; d <<= 1) {
        unsigned u = __shfl_up_sync(0xFFFFFFFFu, inc, d);
        if (lane >= d) inc += u;
    }
    if (lane == 31) s_wsum[wid] = inc;
    __syncthreads();
    if (wid == 0 && lane < 8) {
        unsigned w = s_wsum[lane];
        #pragma unroll
        for (int d = 1; d < 8; d <<= 1) {
            unsigned u = __shfl_up_sync(0xFFu, w, d);
            if (lane >= d) w += u;
        }
        s_wsum[lane] = w;
    }
    __syncthreads();

    unsigned warp_excl = (wid > 0) ? s_wsum[wid - 1] : 0u;
    unsigned running = s_base + warp_excl + (inc - tsum);

    if (full) {
        int4* po = reinterpret_cast<int4*>(g_off + base);
        #pragma unroll
        for (int q = 0; q < SCAN_ITEMS / 4; ++q) {
            int4 o;
            o.x = (int)running; running += (unsigned)items[q * 4 + 0];
            o.y = (int)running; running += (unsigned)items[q * 4 + 1];
            o.z = (int)running; running += (unsigned)items[q * 4 + 2];
            o.w = (int)running; running += (unsigned)items[q * 4 + 3];
            po[q] = o;
        }
    } else {
        #pragma unroll
        for (int q = 0; q < SCAN_ITEMS; ++q) {
            if (base + q < n) g_off[base + q] = (int)running;
            running += (unsigned)items[q];
        }
    }
}

// ---------------------------------------------------------------------------
// K3: atomic-free bucket fill: pos = g_off[dst] + precomputed rank.
// Pure load/gather/scatter — fully pipelined, no L2-atomic round trips.
// ---------------------------------------------------------------------------
__global__ void k_fill(const int* __restrict__ src,
                       const int* __restrict__ dst, int nE) {
    int t = blockIdx.x * blockDim.x + threadIdx.x;
    int i4 = t * 4;
    if (i4 + 4 <= nE) {
        int4 d = *reinterpret_cast<const int4*>(dst + i4);
        int4 s = *reinterpret_cast<const int4*>(src + i4);
        int4 r = *reinterpret_cast<const int4*>(g_rank + i4);
        int o0 = __ldg(&g_off[d.x]);
        int o1 = __ldg(&g_off[d.y]);
        int o2 = __ldg(&g_off[d.z]);
        int o3 = __ldg(&g_off[d.w]);
        g_ssrc[o0 + r.x] = s.x;
        g_ssrc[o1 + r.y] = s.y;
        g_ssrc[o2 + r.z] = s.z;
        g_ssrc[o3 + r.w] = s.w;
    } else {
        for (int i = i4; i < nE; ++i)
            g_ssrc[g_off[dst[i]] + g_rank[i]] = src[i];
    }
}

// ---------------------------------------------------------------------------
// K4: aggregation. One 16-lane group per node; each lane owns a float4 of
// the 64-float row. Edge indices broadcast-loaded by all lanes; 8 gathers
// kept in flight.
// ---------------------------------------------------------------------------
__global__ __launch_bounds__(256) void k_agg(const float* __restrict__ x, int n) {
    int node = (blockIdx.x * blockDim.x + threadIdx.x) >> 4;
    int l = threadIdx.x & 15;
    if (node >= n) return;

    int begin = g_off[node];
    int end   = g_off[node + 1];
    const float4* xv = reinterpret_cast<const float4*>(x);

    float4 acc = make_float4(0.f, 0.f, 0.f, 0.f);
    int i = begin;

    #pragma unroll 1
    for (; i + 8 <= end; i += 8) {
        int e0 = __ldg(&g_ssrc[i + 0]);
        int e1 = __ldg(&g_ssrc[i + 1]);
        int e2 = __ldg(&g_ssrc[i + 2]);
        int e3 = __ldg(&g_ssrc[i + 3]);
        int e4 = __ldg(&g_ssrc[i + 4]);
        int e5 = __ldg(&g_ssrc[i + 5]);
        int e6 = __ldg(&g_ssrc[i + 6]);
        int e7 = __ldg(&g_ssrc[i + 7]);
        float4 v0 = xv[(size_t)e0 * 16 + l];
        float4 v1 = xv[(size_t)e1 * 16 + l];
        float4 v2 = xv[(size_t)e2 * 16 + l];
        float4 v3 = xv[(size_t)e3 * 16 + l];
        float4 v4 = xv[(size_t)e4 * 16 + l];
        float4 v5 = xv[(size_t)e5 * 16 + l];
        float4 v6 = xv[(size_t)e6 * 16 + l];
        float4 v7 = xv[(size_t)e7 * 16 + l];
        acc.x += ((v0.x + v1.x) + (v2.x + v3.x)) + ((v4.x + v5.x) + (v6.x + v7.x));
        acc.y += ((v0.y + v1.y) + (v2.y + v3.y)) + ((v4.y + v5.y) + (v6.y + v7.y));
        acc.z += ((v0.z + v1.z) + (v2.z + v3.z)) + ((v4.z + v5.z) + (v6.z + v7.z));
        acc.w += ((v0.w + v1.w) + (v2.w + v3.w)) + ((v4.w + v5.w) + (v6.w + v7.w));
    }
    if (i + 4 <= end) {
        int e0 = __ldg(&g_ssrc[i + 0]);
        int e1 = __ldg(&g_ssrc[i + 1]);
        int e2 = __ldg(&g_ssrc[i + 2]);
        int e3 = __ldg(&g_ssrc[i + 3]);
        float4 v0 = xv[(size_t)e0 * 16 + l];
        float4 v1 = xv[(size_t)e1 * 16 + l];
        float4 v2 = xv[(size_t)e2 * 16 + l];
        float4 v3 = xv[(size_t)e3 * 16 + l];
        acc.x += (v0.x + v1.x) + (v2.x + v3.x);
        acc.y += (v0.y + v1.y) + (v2.y + v3.y);
        acc.z += (v0.z + v1.z) + (v2.z + v3.z);
        acc.w += (v0.w + v1.w) + (v2.w + v3.w);
        i += 4;
    }
    #pragma unroll 1
    for (; i < end; ++i) {
        int e0 = __ldg(&g_ssrc[i]);
        float4 v0 = xv[(size_t)e0 * 16 + l];
        acc.x += v0.x; acc.y += v0.y; acc.z += v0.z; acc.w += v0.w;
    }

    float invd = 1.0f / fmaxf((float)(end - begin), 1.0f);
    acc.x *= invd; acc.y *= invd; acc.z *= invd; acc.w *= invd;
    *reinterpret_cast<float4*>(g_h + (size_t)node * DIM + l * 4) = acc;
}

// ---------------------------------------------------------------------------
// K5: linear out = h @ W^T + b. 64x64 tile per 256-thread block, 4x4
// register tiles, float4 smem loads.
// ---------------------------------------------------------------------------
__global__ __launch_bounds__(256) void k_gemm(
    const float* __restrict__ W, const float* __restrict__ b,
    float* __restrict__ out, int nNodes) {
    __shared__ float sW[DIM][68];
    __shared__ float sh[DIM][68];
    int tid = threadIdx.x;

    for (int i = tid; i < DIM * DIM; i += 256) {
        int j = i >> 6;
        int k = i & 63;
        sW[k][j] = W[i];
    }

    int n0 = blockIdx.x * 64;
    #pragma unroll
    for (int r = 0; r < 16; ++r) {
        int flat = r * 256 + tid;
        int nl = flat >> 6;
        int k  = flat & 63;
        int n = n0 + nl;
        float v = 0.f;
        if (n < nNodes) v = g_h[(size_t)n * DIM + k];
        sh[k][nl] = v;
    }
    __syncthreads();

    int tx = tid & 15;
    int ty = tid >> 4;
    int jc  = tx * 4;
    int nl0 = ty * 4;

    float accum[4][4];
    float4 bb = *reinterpret_cast<const float4*>(b + jc);
    #pragma unroll
    for (int a = 0; a < 4; ++a) {
        accum[a][0] = bb.x; accum[a][1] = bb.y;
        accum[a][2] = bb.z; accum[a][3] = bb.w;
    }

    #pragma unroll
    for (int k = 0; k < DIM; ++k) {
        float4 hv = *reinterpret_cast<const float4*>(&sh[k][nl0]);
        float4 wv = *reinterpret_cast<const float4*>(&sW[k][jc]);
        float ha[4] = {hv.x, hv.y, hv.z, hv.w};
        float wa[4] = {wv.x, wv.y, wv.z, wv.w};
        #pragma unroll
        for (int a = 0; a < 4; ++a)
            #pragma unroll
            for (int c2 = 0; c2 < 4; ++c2)
                accum[a][c2] += ha[a] * wa[c2];
    }

    #pragma unroll
    for (int a = 0; a < 4; ++a) {
        int n = n0 + nl0 + a;
        if (n < nNodes) {
            float4 o = make_float4(accum[a][0], accum[a][1],
                                   accum[a][2], accum[a][3]);
            *reinterpret_cast<float4*>(out + (size_t)n * DIM + jc) = o;
        }
    }
}

// ---------------------------------------------------------------------------
// Launch. Inputs: x [N*64 f32], src [E i32], dst [E i32], W [64*64 f32],
// b [64 f32]. Output: [N*64 f32].
// ---------------------------------------------------------------------------
extern "C" void kernel_launch(void* const* d_in, const int* in_sizes, int n_in,
                              void* d_out, int out_size) {
    const float* x   = (const float*)d_in[0];
    const int*   src = (const int*)d_in[1];
    const int*   dst = (const int*)d_in[2];
    const float* W   = (const float*)d_in[3];
    const float* b   = (const float*)d_in[4];
    float* out = (float*)d_out;

    int nNodes = in_sizes[0] / DIM;
    int nEdges = in_sizes[1];

    int e4Blocks = ((nEdges + 3) / 4 + 255) / 256;
    int scanTiles = (nNodes + SCAN_TILE - 1) / SCAN_TILE;

    k_hist<<<e4Blocks, 256>>>(dst, nEdges, nNodes);
    k_reduce<<<scanTiles, SCAN_TPB>>>(nNodes);
    k_scan<<<scanTiles, SCAN_TPB>>>(nNodes);
    k_fill<<<e4Blocks, 256>>>(src, dst, nEdges);
    k_agg<<<(nNodes * 16 + 255) / 256, 256>>>(x, nNodes);
    k_gemm<<<(nNodes + 63) / 64, 256>>>(W, b, out, nNodes);
}